// round 7
// baseline (speedup 1.0000x reference)
#include <cuda_runtime.h>
#include <cuda_fp16.h>
#include <cstdint>

#define H 768
#define BATCHN 128
#define TM 128          // i rows per CTA
#define TNO 128         // output-col (k) block per ct
#define TKC 32          // contraction chunk (j) per step
#define NSEG (H / TKC)  // 24
#define NCT (H / TNO)   // 6
#define NT (NCT * NSEG) // 144 flattened steps
#define NTHREADS 256

// SMEM: per stage 3 tiles (h, S_h, S_l), 128 rows x 80B pitch (64B data + pad)
#define ROWB 80
#define TILE_B (128 * ROWB)            // 10240
#define OFF_H  0
#define OFF_SH (TILE_B)
#define OFF_SL (2 * TILE_B)
#define STAGE_B (3 * TILE_B)           // 30720
#define NSTAGE 3
#define OFF_SP (NSTAGE * STAGE_B)      // partials: 4*128 floats
#define SMEM_TOTAL (OFF_SP + 4 * 128 * 4)   // 94208

__device__ float g_logits[BATCHN * H];
__device__ __half g_sh[(size_t)BATCHN * H * H];   // sym(A) hi
__device__ __half g_sl[(size_t)BATCHN * H * H];   // sym(A) lo
__device__ __half g_op_hi[H * H];
__device__ __half g_op_lo[H * H];

// ---------------- helpers ----------------
__device__ __forceinline__ uint32_t smem_u32(const void* p) {
    uint32_t a;
    asm("{ .reg .u64 t; cvta.to.shared.u64 t, %1; cvt.u32.u64 %0, t; }" : "=r"(a) : "l"(p));
    return a;
}
__device__ __forceinline__ void ldsm4(uint32_t* r, uint32_t addr) {
    asm volatile("ldmatrix.sync.aligned.m8n8.x4.shared.b16 {%0,%1,%2,%3}, [%4];"
                 : "=r"(r[0]), "=r"(r[1]), "=r"(r[2]), "=r"(r[3]) : "r"(addr));
}
__device__ __forceinline__ void mma16816(float* d, const uint32_t* a, const uint32_t* b) {
    asm volatile(
        "mma.sync.aligned.m16n8k16.row.col.f32.f16.f16.f32 "
        "{%0,%1,%2,%3}, {%4,%5,%6,%7}, {%8,%9}, {%0,%1,%2,%3};"
        : "+f"(d[0]), "+f"(d[1]), "+f"(d[2]), "+f"(d[3])
        : "r"(a[0]), "r"(a[1]), "r"(a[2]), "r"(a[3]), "r"(b[0]), "r"(b[1]));
}
__device__ __forceinline__ void cp16(uint32_t dst, const void* src) {
    asm volatile("cp.async.cg.shared.global [%0], [%1], 16;" :: "r"(dst), "l"(src));
}
__device__ __forceinline__ void cp_commit() { asm volatile("cp.async.commit_group;" ::: "memory"); }
__device__ __forceinline__ void cp_wait1()  { asm volatile("cp.async.wait_group 1;" ::: "memory"); }
__device__ __forceinline__ void cp_wait0()  { asm volatile("cp.async.wait_group 0;" ::: "memory"); }
__device__ __forceinline__ uint32_t pack2(__half a, __half b) {
    __half2 h = __halves2half2(a, b);
    return *reinterpret_cast<uint32_t*>(&h);
}
__device__ __forceinline__ void split2(float s0, float s1, uint32_t& hi, uint32_t& lo) {
    __half h0 = __float2half_rn(s0), h1 = __float2half_rn(s1);
    __half l0 = __float2half_rn(s0 - __half2float(h0));
    __half l1 = __float2half_rn(s1 - __half2float(h1));
    hi = pack2(h0, h1);
    lo = pack2(l0, l1);
}

// ---------------- pre-pass 1: symmetrize inputs + fp16 hi/lo split ----------------
__global__ void __launch_bounds__(256)
Measurement_68307159875839_sym(const float* __restrict__ A) {
    const int jt = blockIdx.x, kt = blockIdx.y;
    if (jt > kt) return;
    __shared__ float sA[32][33], sB[32][33];
    const int b = blockIdx.z;
    const float* Ab = A + (size_t)b * H * H;
    __half* sh = g_sh + (size_t)b * H * H;
    __half* sl = g_sl + (size_t)b * H * H;
    const int t = threadIdx.x;
    const int j0 = jt * 32, k0 = kt * 32;
    {
        const int r = t >> 3, q = t & 7;
        float4 va = *reinterpret_cast<const float4*>(Ab + (size_t)(j0 + r) * H + k0 + q * 4);
        sA[r][q * 4 + 0] = va.x; sA[r][q * 4 + 1] = va.y;
        sA[r][q * 4 + 2] = va.z; sA[r][q * 4 + 3] = va.w;
        float4 vb = *reinterpret_cast<const float4*>(Ab + (size_t)(k0 + r) * H + j0 + q * 4);
        sB[r][q * 4 + 0] = vb.x; sB[r][q * 4 + 1] = vb.y;
        sB[r][q * 4 + 2] = vb.z; sB[r][q * 4 + 3] = vb.w;
    }
    __syncthreads();
    const int r16 = t >> 4, cp = t & 15;
#pragma unroll
    for (int rr = 0; rr < 2; rr++) {
        const int row = rr * 16 + r16;
        float s0 = 0.5f * (sA[row][2 * cp]     + sB[2 * cp][row]);
        float s1 = 0.5f * (sA[row][2 * cp + 1] + sB[2 * cp + 1][row]);
        uint32_t hi, lo;
        split2(s0, s1, hi, lo);
        size_t off = (size_t)(j0 + row) * H + k0 + 2 * cp;
        *reinterpret_cast<uint32_t*>(sh + off) = hi;
        *reinterpret_cast<uint32_t*>(sl + off) = lo;
        if (jt != kt) {
            float t0 = 0.5f * (sB[row][2 * cp]     + sA[2 * cp][row]);
            float t1 = 0.5f * (sB[row][2 * cp + 1] + sA[2 * cp + 1][row]);
            split2(t0, t1, hi, lo);
            size_t off2 = (size_t)(k0 + row) * H + j0 + 2 * cp;
            *reinterpret_cast<uint32_t*>(sh + off2) = hi;
            *reinterpret_cast<uint32_t*>(sl + off2) = lo;
        }
    }
}

// ---------------- pre-pass 2: op fp32 -> fp16 hi/lo ----------------
__global__ void Measurement_68307159875839_cvt(const float* __restrict__ src,
                                               __half* __restrict__ dst_hi,
                                               __half* __restrict__ dst_lo, int n4) {
    int idx = blockIdx.x * blockDim.x + threadIdx.x;
    if (idx >= n4) return;
    float4 v = reinterpret_cast<const float4*>(src)[idx];
    uint32_t h0, l0, h1, l1;
    split2(v.x, v.y, h0, l0);
    split2(v.z, v.w, h1, l1);
    reinterpret_cast<uint2*>(dst_hi)[idx] = make_uint2(h0, h1);
    reinterpret_cast<uint2*>(dst_lo)[idx] = make_uint2(l0, l1);
}

// ---------------- GEMM (2 products) + fused diag ----------------
__device__ __forceinline__ void fill_stage(uint32_t smem_base, int t, int i0,
                                           size_t s_off, int tid) {
    const int n0 = (t / NSEG) * TNO;
    const int k0 = (t % NSEG) * TKC;
    const int s = t % NSTAGE;
#pragma unroll
    for (int r = 0; r < 6; r++) {
        int q = r * NTHREADS + tid;          // 1536 chunks: 3 tiles x 128 rows x 4 x 16B
        int tile = q >> 9;
        int rem = q & 511;
        int row = rem >> 2;
        int c = rem & 3;
        uint32_t dst = smem_base + (uint32_t)(s * STAGE_B + tile * TILE_B + row * ROWB + c * 16);
        const __half* src;
        if (tile == 0)      src = g_op_hi + (size_t)(i0 + row) * H + k0 + c * 8;
        else if (tile == 1) src = g_sh + s_off + (size_t)(n0 + row) * H + k0 + c * 8;
        else                src = g_sl + s_off + (size_t)(n0 + row) * H + k0 + c * 8;
        cp16(dst, src);
    }
}

// grid: (H/TM = 6, BATCHN = 128); warp tile M=64 x N=32 (2 mw x 4 nw)
__global__ void __launch_bounds__(NTHREADS)
Measurement_68307159875839_gemm(const float* __restrict__ op) {
    extern __shared__ __align__(16) char smem[];
    const uint32_t smem_base = smem_u32(smem);
    const int tid = threadIdx.x;
    const int lane = tid & 31;
    const int w = tid >> 5;
    const int mw = w >> 2;         // 2 M-warps (i): 64 rows each
    const int nw = w & 3;          // 4 N-warps (k): 32 cols each
    const int i0 = blockIdx.x * TM;
    const int b = blockIdx.y;
    const size_t s_off = (size_t)b * H * H;

    const uint32_t a_off = (uint32_t)((mw * 64 + (lane & 15)) * ROWB + (lane >> 4) * 16);
    const uint32_t b_off = (uint32_t)((nw * 32 + (lane & 7) + ((lane & 16) >> 1)) * ROWB +
                                      ((lane >> 3) & 1) * 16);

    float part_acc[4][2];
#pragma unroll
    for (int mt = 0; mt < 4; mt++) { part_acc[mt][0] = 0.f; part_acc[mt][1] = 0.f; }

    float accG1[4][4][4], accG2[4][4][4];
#pragma unroll
    for (int mt = 0; mt < 4; mt++)
#pragma unroll
        for (int nt = 0; nt < 4; nt++)
#pragma unroll
            for (int e = 0; e < 4; e++) { accG1[mt][nt][e] = 0.f; accG2[mt][nt][e] = 0.f; }

    fill_stage(smem_base, 0, i0, s_off, tid); cp_commit();
    fill_stage(smem_base, 1, i0, s_off, tid); cp_commit();

    for (int t = 0; t < NT; ++t) {
        if (t + 1 < NT) cp_wait1(); else cp_wait0();
        __syncthreads();

        const uint32_t sb = smem_base + (uint32_t)((t % NSTAGE) * STAGE_B);
#pragma unroll
        for (int k16 = 0; k16 < 2; k16++) {
            const uint32_t kofs = (uint32_t)(k16 * 32);
            uint32_t ah[4][4];
#pragma unroll
            for (int mt = 0; mt < 4; mt++)
                ldsm4(ah[mt], sb + OFF_H + a_off + mt * 16 * ROWB + kofs);
            uint32_t bh[4][2], bl[4][2];
#pragma unroll
            for (int u = 0; u < 2; u++) {
                uint32_t r4[4];
                ldsm4(r4, sb + OFF_SH + b_off + u * 16 * ROWB + kofs);
                bh[2 * u][0] = r4[0]; bh[2 * u][1] = r4[1];
                bh[2 * u + 1][0] = r4[2]; bh[2 * u + 1][1] = r4[3];
                ldsm4(r4, sb + OFF_SL + b_off + u * 16 * ROWB + kofs);
                bl[2 * u][0] = r4[0]; bl[2 * u][1] = r4[1];
                bl[2 * u + 1][0] = r4[2]; bl[2 * u + 1][1] = r4[3];
            }
#pragma unroll
            for (int mt = 0; mt < 4; mt++)
#pragma unroll
                for (int nt = 0; nt < 4; nt++)
                    mma16816(accG1[mt][nt], ah[mt], bh[nt]);
#pragma unroll
            for (int mt = 0; mt < 4; mt++)
#pragma unroll
                for (int nt = 0; nt < 4; nt++)
                    mma16816(accG2[mt][nt], ah[mt], bl[nt]);
        }
        if (t + 2 < NT) { fill_stage(smem_base, t + 2, i0, s_off, tid); cp_commit(); }

        if ((t % NSEG) == NSEG - 1) {
            // epilogue for this ct: part += sum_k G1*(op+l) + G2*op, then clear acc
            const int n0 = (t / NSEG) * TNO;
#pragma unroll
            for (int mt = 0; mt < 4; mt++)
#pragma unroll
                for (int ir = 0; ir < 2; ir++) {
                    const int i_g = i0 + mw * 64 + mt * 16 + (lane >> 2) + ir * 8;
                    const size_t base = (size_t)i_g * H + n0 + nw * 32 + (lane & 3) * 2;
                    const float* oprow = op + base;
                    const __half* olrow = g_op_lo + base;
                    float s = 0.f;
#pragma unroll
                    for (int nt = 0; nt < 4; nt++) {
                        float2 w2 = *reinterpret_cast<const float2*>(oprow + nt * 8);
                        __half2 lh = *reinterpret_cast<const __half2*>(olrow + nt * 8);
                        float2 l2 = __half22float2(lh);
                        s += accG1[mt][nt][ir * 2 + 0] * (w2.x + l2.x)
                           + accG1[mt][nt][ir * 2 + 1] * (w2.y + l2.y)
                           + accG2[mt][nt][ir * 2 + 0] * w2.x
                           + accG2[mt][nt][ir * 2 + 1] * w2.y;
                    }
                    part_acc[mt][ir] += s;
#pragma unroll
                    for (int nt = 0; nt < 4; nt++) {
                        accG1[mt][nt][ir * 2 + 0] = 0.f; accG1[mt][nt][ir * 2 + 1] = 0.f;
                        accG2[mt][nt][ir * 2 + 0] = 0.f; accG2[mt][nt][ir * 2 + 1] = 0.f;
                    }
                }
        }
    }

    // reduce 4 lanes sharing i, then combine the 4 nw warps via smem
#pragma unroll
    for (int mt = 0; mt < 4; mt++)
#pragma unroll
        for (int ir = 0; ir < 2; ir++) {
            float v = part_acc[mt][ir];
            v += __shfl_xor_sync(0xffffffffu, v, 1);
            v += __shfl_xor_sync(0xffffffffu, v, 2);
            part_acc[mt][ir] = v;
        }
    float* sp = reinterpret_cast<float*>(smem + OFF_SP);
    if ((lane & 3) == 0) {
#pragma unroll
        for (int mt = 0; mt < 4; mt++)
#pragma unroll
            for (int ir = 0; ir < 2; ir++) {
                int i_loc = mw * 64 + mt * 16 + (lane >> 2) + ir * 8;
                sp[nw * 128 + i_loc] = part_acc[mt][ir];
            }
    }
    __syncthreads();
    for (int i = tid; i < TM; i += NTHREADS)
        g_logits[b * H + i0 + i] = (sp[i] + sp[128 + i]) + (sp[256 + i] + sp[384 + i]);
}

// ---------------- softmax ----------------
__global__ void Measurement_68307159875839_softmax(float* __restrict__ out) {
    __shared__ float red[NTHREADS / 32];
    const int b = blockIdx.x, tid = threadIdx.x;
    const float* row = g_logits + b * H;
    float m = -1e30f;
    for (int i = tid; i < H; i += NTHREADS) m = fmaxf(m, row[i]);
#pragma unroll
    for (int o = 16; o > 0; o >>= 1) m = fmaxf(m, __shfl_xor_sync(0xffffffffu, m, o));
    if ((tid & 31) == 0) red[tid >> 5] = m;
    __syncthreads();
    m = red[0];
#pragma unroll
    for (int wv = 1; wv < NTHREADS / 32; wv++) m = fmaxf(m, red[wv]);
    __syncthreads();
    float s = 0.0f;
    for (int i = tid; i < H; i += NTHREADS) s += __expf(row[i] - m);
#pragma unroll
    for (int o = 16; o > 0; o >>= 1) s += __shfl_xor_sync(0xffffffffu, s, o);
    if ((tid & 31) == 0) red[tid >> 5] = s;
    __syncthreads();
    s = 0.0f;
#pragma unroll
    for (int wv = 0; wv < NTHREADS / 32; wv++) s += red[wv];
    const float inv = 1.0f / s;
    for (int i = tid; i < H; i += NTHREADS) out[b * H + i] = __expf(row[i] - m) * inv;
}

extern "C" void kernel_launch(void* const* d_in, const int* in_sizes, int n_in,
                              void* d_out, int out_size) {
    const float* inputs = (const float*)d_in[0];   // [128, 768, 768] fp32
    const float* op     = (const float*)d_in[1];   // [768, 768] fp32
    float* out = (float*)d_out;                    // [128, 768] fp32
    static int configured = 0;
    if (!configured) {
        cudaFuncSetAttribute(Measurement_68307159875839_gemm,
                             cudaFuncAttributeMaxDynamicSharedMemorySize, SMEM_TOTAL);
        configured = 1;
    }
    __half *op_hi, *op_lo;
    cudaGetSymbolAddress((void**)&op_hi, g_op_hi);
    cudaGetSymbolAddress((void**)&op_lo, g_op_lo);

    const int n4_op = H * H / 4;            // 147,456
    Measurement_68307159875839_sym<<<dim3(H / 32, H / 32, BATCHN), 256>>>(inputs);
    Measurement_68307159875839_cvt<<<(n4_op + 255) / 256, 256>>>(op, op_hi, op_lo, n4_op);
    Measurement_68307159875839_gemm<<<dim3(H / TM, BATCHN), NTHREADS, SMEM_TOTAL>>>(op);
    Measurement_68307159875839_softmax<<<BATCHN, NTHREADS>>>(out);
}

// round 8
// speedup vs baseline: 1.2533x; 1.2533x over previous
#include <cuda_runtime.h>
#include <cuda_fp16.h>
#include <cstdint>

#define H 768
#define BATCHN 128
#define TM 128          // i rows per CTA
#define TNO 128         // output-col (k) block per ct
#define TKC 32          // contraction chunk (j) per step
#define NSEG (H / TKC)  // 24
#define CT_PER_TASK 2
#define NT (CT_PER_TASK * NSEG)  // 48 steps per task
#define NXB ((H / TM) * (H / TNO / CT_PER_TASK))   // 6 * 3 = 18
#define NTHREADS 256

// SMEM: per stage 3 tiles (h, S_h, S_l), 128 rows x 80B pitch (64B data + pad)
#define ROWB 80
#define TILE_B (128 * ROWB)            // 10240
#define OFF_H  0
#define OFF_SH (TILE_B)
#define OFF_SL (2 * TILE_B)
#define STAGE_B (3 * TILE_B)           // 30720
#define NSTAGE 3
#define OFF_SP (NSTAGE * STAGE_B)      // partials: 4*128 floats
#define SMEM_TOTAL (OFF_SP + 4 * 128 * 4)   // 94208

__device__ float g_logits[BATCHN * H];
__device__ __half g_sh[(size_t)BATCHN * H * H];   // sym(A) hi
__device__ __half g_sl[(size_t)BATCHN * H * H];   // sym(A) lo
__device__ __half g_op_hi[H * H];
__device__ __half g_op_lo[H * H];

// ---------------- helpers ----------------
__device__ __forceinline__ uint32_t smem_u32(const void* p) {
    uint32_t a;
    asm("{ .reg .u64 t; cvta.to.shared.u64 t, %1; cvt.u32.u64 %0, t; }" : "=r"(a) : "l"(p));
    return a;
}
__device__ __forceinline__ void ldsm4(uint32_t* r, uint32_t addr) {
    asm volatile("ldmatrix.sync.aligned.m8n8.x4.shared.b16 {%0,%1,%2,%3}, [%4];"
                 : "=r"(r[0]), "=r"(r[1]), "=r"(r[2]), "=r"(r[3]) : "r"(addr));
}
__device__ __forceinline__ void mma16816(float* d, const uint32_t* a, const uint32_t* b) {
    asm volatile(
        "mma.sync.aligned.m16n8k16.row.col.f32.f16.f16.f32 "
        "{%0,%1,%2,%3}, {%4,%5,%6,%7}, {%8,%9}, {%0,%1,%2,%3};"
        : "+f"(d[0]), "+f"(d[1]), "+f"(d[2]), "+f"(d[3])
        : "r"(a[0]), "r"(a[1]), "r"(a[2]), "r"(a[3]), "r"(b[0]), "r"(b[1]));
}
// fp16-accumulate variant (G2 low-order product): D,C = 2x b32 (4 halves)
__device__ __forceinline__ void mma16816h(uint32_t* d, const uint32_t* a, const uint32_t* b) {
    asm volatile(
        "mma.sync.aligned.m16n8k16.row.col.f16.f16.f16.f16 "
        "{%0,%1}, {%2,%3,%4,%5}, {%6,%7}, {%0,%1};"
        : "+r"(d[0]), "+r"(d[1])
        : "r"(a[0]), "r"(a[1]), "r"(a[2]), "r"(a[3]), "r"(b[0]), "r"(b[1]));
}
__device__ __forceinline__ void cp16(uint32_t dst, const void* src) {
    asm volatile("cp.async.cg.shared.global [%0], [%1], 16;" :: "r"(dst), "l"(src));
}
__device__ __forceinline__ void cp_commit() { asm volatile("cp.async.commit_group;" ::: "memory"); }
__device__ __forceinline__ void cp_wait1()  { asm volatile("cp.async.wait_group 1;" ::: "memory"); }
__device__ __forceinline__ void cp_wait0()  { asm volatile("cp.async.wait_group 0;" ::: "memory"); }
__device__ __forceinline__ uint32_t pack2(__half a, __half b) {
    __half2 h = __halves2half2(a, b);
    return *reinterpret_cast<uint32_t*>(&h);
}
__device__ __forceinline__ void split2(float s0, float s1, uint32_t& hi, uint32_t& lo) {
    __half h0 = __float2half_rn(s0), h1 = __float2half_rn(s1);
    __half l0 = __float2half_rn(s0 - __half2float(h0));
    __half l1 = __float2half_rn(s1 - __half2float(h1));
    hi = pack2(h0, h1);
    lo = pack2(l0, l1);
}

// ---------------- pre-pass 1: symmetrize inputs + fp16 hi/lo split ----------------
__global__ void __launch_bounds__(256)
Measurement_68307159875839_sym(const float* __restrict__ A) {
    const int jt = blockIdx.x, kt = blockIdx.y;
    if (jt > kt) return;
    __shared__ float sA[32][33], sB[32][33];
    const int b = blockIdx.z;
    const float* Ab = A + (size_t)b * H * H;
    __half* sh = g_sh + (size_t)b * H * H;
    __half* sl = g_sl + (size_t)b * H * H;
    const int t = threadIdx.x;
    const int j0 = jt * 32, k0 = kt * 32;
    {
        const int r = t >> 3, q = t & 7;
        float4 va = *reinterpret_cast<const float4*>(Ab + (size_t)(j0 + r) * H + k0 + q * 4);
        sA[r][q * 4 + 0] = va.x; sA[r][q * 4 + 1] = va.y;
        sA[r][q * 4 + 2] = va.z; sA[r][q * 4 + 3] = va.w;
        float4 vb = *reinterpret_cast<const float4*>(Ab + (size_t)(k0 + r) * H + j0 + q * 4);
        sB[r][q * 4 + 0] = vb.x; sB[r][q * 4 + 1] = vb.y;
        sB[r][q * 4 + 2] = vb.z; sB[r][q * 4 + 3] = vb.w;
    }
    __syncthreads();
    const int r16 = t >> 4, cp = t & 15;
#pragma unroll
    for (int rr = 0; rr < 2; rr++) {
        const int row = rr * 16 + r16;
        float s0 = 0.5f * (sA[row][2 * cp]     + sB[2 * cp][row]);
        float s1 = 0.5f * (sA[row][2 * cp + 1] + sB[2 * cp + 1][row]);
        uint32_t hi, lo;
        split2(s0, s1, hi, lo);
        size_t off = (size_t)(j0 + row) * H + k0 + 2 * cp;
        *reinterpret_cast<uint32_t*>(sh + off) = hi;
        *reinterpret_cast<uint32_t*>(sl + off) = lo;
        if (jt != kt) {
            float t0 = 0.5f * (sB[row][2 * cp]     + sA[2 * cp][row]);
            float t1 = 0.5f * (sB[row][2 * cp + 1] + sA[2 * cp + 1][row]);
            split2(t0, t1, hi, lo);
            size_t off2 = (size_t)(k0 + row) * H + j0 + 2 * cp;
            *reinterpret_cast<uint32_t*>(sh + off2) = hi;
            *reinterpret_cast<uint32_t*>(sl + off2) = lo;
        }
    }
}

// ---------------- pre-pass 2: op fp32 -> fp16 hi/lo, + zero logits ----------------
__global__ void Measurement_68307159875839_cvt(const float* __restrict__ src,
                                               __half* __restrict__ dst_hi,
                                               __half* __restrict__ dst_lo, int n4) {
    int idx = blockIdx.x * blockDim.x + threadIdx.x;
    if (idx < BATCHN * H) g_logits[idx] = 0.0f;
    if (idx >= n4) return;
    float4 v = reinterpret_cast<const float4*>(src)[idx];
    uint32_t h0, l0, h1, l1;
    split2(v.x, v.y, h0, l0);
    split2(v.z, v.w, h1, l1);
    reinterpret_cast<uint2*>(dst_hi)[idx] = make_uint2(h0, h1);
    reinterpret_cast<uint2*>(dst_lo)[idx] = make_uint2(l0, l1);
}

// ---------------- GEMM (2 products; G2 in f16-acc) + fused diag ----------------
__device__ __forceinline__ void fill_stage(uint32_t smem_base, int t, int i0, int ct_base,
                                           size_t s_off, int tid) {
    const int n0 = (ct_base + t / NSEG) * TNO;
    const int k0 = (t % NSEG) * TKC;
    const int s = t % NSTAGE;
#pragma unroll
    for (int r = 0; r < 6; r++) {
        int q = r * NTHREADS + tid;          // 1536 chunks: 3 tiles x 128 rows x 4 x 16B
        int tile = q >> 9;
        int rem = q & 511;
        int row = rem >> 2;
        int c = rem & 3;
        uint32_t dst = smem_base + (uint32_t)(s * STAGE_B + tile * TILE_B + row * ROWB + c * 16);
        const __half* src;
        if (tile == 0)      src = g_op_hi + (size_t)(i0 + row) * H + k0 + c * 8;
        else if (tile == 1) src = g_sh + s_off + (size_t)(n0 + row) * H + k0 + c * 8;
        else                src = g_sl + s_off + (size_t)(n0 + row) * H + k0 + c * 8;
        cp16(dst, src);
    }
}

// grid: (18, 128): x = i-tile (6) x ct-pair (3); y = batch. warp tile M=64 x N=32.
__global__ void __launch_bounds__(NTHREADS)
Measurement_68307159875839_gemm(const float* __restrict__ op) {
    extern __shared__ __align__(16) char smem[];
    const uint32_t smem_base = smem_u32(smem);
    const int tid = threadIdx.x;
    const int lane = tid & 31;
    const int w = tid >> 5;
    const int mw = w >> 2;         // 2 M-warps (i): 64 rows each
    const int nw = w & 3;          // 4 N-warps (k): 32 cols each
    const int i0 = (blockIdx.x % 6) * TM;
    const int ct_base = (blockIdx.x / 6) * CT_PER_TASK;
    const int b = blockIdx.y;
    const size_t s_off = (size_t)b * H * H;

    const uint32_t a_off = (uint32_t)((mw * 64 + (lane & 15)) * ROWB + (lane >> 4) * 16);
    const uint32_t b_off = (uint32_t)((nw * 32 + (lane & 7) + ((lane & 16) >> 1)) * ROWB +
                                      ((lane >> 3) & 1) * 16);

    float part_acc[4][2];
#pragma unroll
    for (int mt = 0; mt < 4; mt++) { part_acc[mt][0] = 0.f; part_acc[mt][1] = 0.f; }

    float accG1[4][4][4];
    uint32_t accG2[4][4][2];        // f16x2 accumulators
#pragma unroll
    for (int mt = 0; mt < 4; mt++)
#pragma unroll
        for (int nt = 0; nt < 4; nt++) {
#pragma unroll
            for (int e = 0; e < 4; e++) accG1[mt][nt][e] = 0.f;
            accG2[mt][nt][0] = 0u; accG2[mt][nt][1] = 0u;
        }

    fill_stage(smem_base, 0, i0, ct_base, s_off, tid); cp_commit();
    fill_stage(smem_base, 1, i0, ct_base, s_off, tid); cp_commit();

    for (int t = 0; t < NT; ++t) {
        if (t + 1 < NT) cp_wait1(); else cp_wait0();
        __syncthreads();

        const uint32_t sb = smem_base + (uint32_t)((t % NSTAGE) * STAGE_B);
#pragma unroll
        for (int k16 = 0; k16 < 2; k16++) {
            const uint32_t kofs = (uint32_t)(k16 * 32);
            uint32_t ah[4][4];
#pragma unroll
            for (int mt = 0; mt < 4; mt++)
                ldsm4(ah[mt], sb + OFF_H + a_off + mt * 16 * ROWB + kofs);
            uint32_t bh[4][2], bl[4][2];
#pragma unroll
            for (int u = 0; u < 2; u++) {
                uint32_t r4[4];
                ldsm4(r4, sb + OFF_SH + b_off + u * 16 * ROWB + kofs);
                bh[2 * u][0] = r4[0]; bh[2 * u][1] = r4[1];
                bh[2 * u + 1][0] = r4[2]; bh[2 * u + 1][1] = r4[3];
                ldsm4(r4, sb + OFF_SL + b_off + u * 16 * ROWB + kofs);
                bl[2 * u][0] = r4[0]; bl[2 * u][1] = r4[1];
                bl[2 * u + 1][0] = r4[2]; bl[2 * u + 1][1] = r4[3];
            }
#pragma unroll
            for (int mt = 0; mt < 4; mt++)
#pragma unroll
                for (int nt = 0; nt < 4; nt++)
                    mma16816(accG1[mt][nt], ah[mt], bh[nt]);
#pragma unroll
            for (int mt = 0; mt < 4; mt++)
#pragma unroll
                for (int nt = 0; nt < 4; nt++)
                    mma16816h(accG2[mt][nt], ah[mt], bl[nt]);
        }
        if (t + 2 < NT) { fill_stage(smem_base, t + 2, i0, ct_base, s_off, tid); cp_commit(); }

        if ((t % NSEG) == NSEG - 1) {
            // epilogue for this ct: part += sum_k G1*(op+l) + G2*op, then clear acc
            const int n0 = (ct_base + t / NSEG) * TNO;
#pragma unroll
            for (int mt = 0; mt < 4; mt++)
#pragma unroll
                for (int ir = 0; ir < 2; ir++) {
                    const int i_g = i0 + mw * 64 + mt * 16 + (lane >> 2) + ir * 8;
                    const size_t base = (size_t)i_g * H + n0 + nw * 32 + (lane & 3) * 2;
                    const float* oprow = op + base;
                    const __half* olrow = g_op_lo + base;
                    float s = 0.f;
#pragma unroll
                    for (int nt = 0; nt < 4; nt++) {
                        float2 w2 = *reinterpret_cast<const float2*>(oprow + nt * 8);
                        __half2 lh = *reinterpret_cast<const __half2*>(olrow + nt * 8);
                        float2 l2 = __half22float2(lh);
                        __half2 g2h = *reinterpret_cast<__half2*>(&accG2[mt][nt][ir]);
                        float2 g2 = __half22float2(g2h);
                        s += accG1[mt][nt][ir * 2 + 0] * (w2.x + l2.x)
                           + accG1[mt][nt][ir * 2 + 1] * (w2.y + l2.y)
                           + g2.x * w2.x + g2.y * w2.y;
                    }
                    part_acc[mt][ir] += s;
#pragma unroll
                    for (int nt = 0; nt < 4; nt++) {
                        accG1[mt][nt][ir * 2 + 0] = 0.f; accG1[mt][nt][ir * 2 + 1] = 0.f;
                        accG2[mt][nt][ir] = 0u;
                    }
                }
        }
    }

    // reduce 4 lanes sharing i, combine 4 nw warps via smem, one atomicAdd per i
#pragma unroll
    for (int mt = 0; mt < 4; mt++)
#pragma unroll
        for (int ir = 0; ir < 2; ir++) {
            float v = part_acc[mt][ir];
            v += __shfl_xor_sync(0xffffffffu, v, 1);
            v += __shfl_xor_sync(0xffffffffu, v, 2);
            part_acc[mt][ir] = v;
        }
    float* sp = reinterpret_cast<float*>(smem + OFF_SP);
    if ((lane & 3) == 0) {
#pragma unroll
        for (int mt = 0; mt < 4; mt++)
#pragma unroll
            for (int ir = 0; ir < 2; ir++) {
                int i_loc = mw * 64 + mt * 16 + (lane >> 2) + ir * 8;
                sp[nw * 128 + i_loc] = part_acc[mt][ir];
            }
    }
    __syncthreads();
    for (int i = tid; i < TM; i += NTHREADS)
        atomicAdd(&g_logits[b * H + i0 + i],
                  (sp[i] + sp[128 + i]) + (sp[256 + i] + sp[384 + i]));
}

// ---------------- softmax ----------------
__global__ void Measurement_68307159875839_softmax(float* __restrict__ out) {
    __shared__ float red[NTHREADS / 32];
    const int b = blockIdx.x, tid = threadIdx.x;
    const float* row = g_logits + b * H;
    float m = -1e30f;
    for (int i = tid; i < H; i += NTHREADS) m = fmaxf(m, row[i]);
#pragma unroll
    for (int o = 16; o > 0; o >>= 1) m = fmaxf(m, __shfl_xor_sync(0xffffffffu, m, o));
    if ((tid & 31) == 0) red[tid >> 5] = m;
    __syncthreads();
    m = red[0];
#pragma unroll
    for (int wv = 1; wv < NTHREADS / 32; wv++) m = fmaxf(m, red[wv]);
    __syncthreads();
    float s = 0.0f;
    for (int i = tid; i < H; i += NTHREADS) s += __expf(row[i] - m);
#pragma unroll
    for (int o = 16; o > 0; o >>= 1) s += __shfl_xor_sync(0xffffffffu, s, o);
    if ((tid & 31) == 0) red[tid >> 5] = s;
    __syncthreads();
    s = 0.0f;
#pragma unroll
    for (int wv = 0; wv < NTHREADS / 32; wv++) s += red[wv];
    const float inv = 1.0f / s;
    for (int i = tid; i < H; i += NTHREADS) out[b * H + i] = __expf(row[i] - m) * inv;
}

extern "C" void kernel_launch(void* const* d_in, const int* in_sizes, int n_in,
                              void* d_out, int out_size) {
    const float* inputs = (const float*)d_in[0];   // [128, 768, 768] fp32
    const float* op     = (const float*)d_in[1];   // [768, 768] fp32
    float* out = (float*)d_out;                    // [128, 768] fp32
    static int configured = 0;
    if (!configured) {
        cudaFuncSetAttribute(Measurement_68307159875839_gemm,
                             cudaFuncAttributeMaxDynamicSharedMemorySize, SMEM_TOTAL);
        configured = 1;
    }
    __half *op_hi, *op_lo;
    cudaGetSymbolAddress((void**)&op_hi, g_op_hi);
    cudaGetSymbolAddress((void**)&op_lo, g_op_lo);

    const int n4_op = H * H / 4;            // 147,456
    Measurement_68307159875839_sym<<<dim3(H / 32, H / 32, BATCHN), 256>>>(inputs);
    Measurement_68307159875839_cvt<<<(n4_op + 255) / 256, 256>>>(op, op_hi, op_lo, n4_op);
    Measurement_68307159875839_gemm<<<dim3(NXB, BATCHN), NTHREADS, SMEM_TOTAL>>>(op);
    Measurement_68307159875839_softmax<<<BATCHN, NTHREADS>>>(out);
}

// round 9
// speedup vs baseline: 1.2753x; 1.0175x over previous
#include <cuda_runtime.h>
#include <cuda_fp16.h>
#include <cstdint>

#define H 768
#define BATCHN 128
#define NCHUNK 4
#define CHUNK_B (BATCHN / NCHUNK)   // 32
#define TM 128
#define TNO 128
#define TKC 32
#define NSEG (H / TKC)  // 24
#define CT_PER_TASK 2
#define NT (CT_PER_TASK * NSEG)  // 48 steps per task
#define NXB ((H / TM) * (H / TNO / CT_PER_TASK))   // 18
#define NTHREADS 256

#define ROWB 80
#define TILE_B (128 * ROWB)
#define OFF_H  0
#define OFF_SH (TILE_B)
#define OFF_SL (2 * TILE_B)
#define STAGE_B (3 * TILE_B)
#define NSTAGE 3
#define OFF_SP (NSTAGE * STAGE_B)
#define SMEM_TOTAL (OFF_SP + 4 * 128 * 4)   // 94208

__device__ float g_logits[BATCHN * H];
__device__ __half g_sh[(size_t)BATCHN * H * H];
__device__ __half g_sl[(size_t)BATCHN * H * H];
__device__ __half g_op_hi[H * H];
__device__ __half g_op_lo[H * H];

// ---------------- helpers ----------------
__device__ __forceinline__ uint32_t smem_u32(const void* p) {
    uint32_t a;
    asm("{ .reg .u64 t; cvta.to.shared.u64 t, %1; cvt.u32.u64 %0, t; }" : "=r"(a) : "l"(p));
    return a;
}
__device__ __forceinline__ void ldsm4(uint32_t* r, uint32_t addr) {
    asm volatile("ldmatrix.sync.aligned.m8n8.x4.shared.b16 {%0,%1,%2,%3}, [%4];"
                 : "=r"(r[0]), "=r"(r[1]), "=r"(r[2]), "=r"(r[3]) : "r"(addr));
}
__device__ __forceinline__ void mma16816(float* d, const uint32_t* a, const uint32_t* b) {
    asm volatile(
        "mma.sync.aligned.m16n8k16.row.col.f32.f16.f16.f32 "
        "{%0,%1,%2,%3}, {%4,%5,%6,%7}, {%8,%9}, {%0,%1,%2,%3};"
        : "+f"(d[0]), "+f"(d[1]), "+f"(d[2]), "+f"(d[3])
        : "r"(a[0]), "r"(a[1]), "r"(a[2]), "r"(a[3]), "r"(b[0]), "r"(b[1]));
}
__device__ __forceinline__ void mma16816h(uint32_t* d, const uint32_t* a, const uint32_t* b) {
    asm volatile(
        "mma.sync.aligned.m16n8k16.row.col.f16.f16.f16.f16 "
        "{%0,%1}, {%2,%3,%4,%5}, {%6,%7}, {%0,%1};"
        : "+r"(d[0]), "+r"(d[1])
        : "r"(a[0]), "r"(a[1]), "r"(a[2]), "r"(a[3]), "r"(b[0]), "r"(b[1]));
}
__device__ __forceinline__ void cp16(uint32_t dst, const void* src) {
    asm volatile("cp.async.cg.shared.global [%0], [%1], 16;" :: "r"(dst), "l"(src));
}
__device__ __forceinline__ void cp_commit() { asm volatile("cp.async.commit_group;" ::: "memory"); }
__device__ __forceinline__ void cp_wait1()  { asm volatile("cp.async.wait_group 1;" ::: "memory"); }
__device__ __forceinline__ void cp_wait0()  { asm volatile("cp.async.wait_group 0;" ::: "memory"); }
__device__ __forceinline__ uint32_t pack2(__half a, __half b) {
    __half2 h = __halves2half2(a, b);
    return *reinterpret_cast<uint32_t*>(&h);
}
__device__ __forceinline__ void split2(float s0, float s1, uint32_t& hi, uint32_t& lo) {
    __half h0 = __float2half_rn(s0), h1 = __float2half_rn(s1);
    __half l0 = __float2half_rn(s0 - __half2float(h0));
    __half l1 = __float2half_rn(s1 - __half2float(h1));
    hi = pack2(h0, h1);
    lo = pack2(l0, l1);
}

// ---------------- sym: symmetrize inputs chunk + fp16 hi/lo split ----------------
__global__ void __launch_bounds__(256)
Measurement_68307159875839_sym(const float* __restrict__ A, int b0) {
    const int jt = blockIdx.x, kt = blockIdx.y;
    if (jt > kt) return;
    __shared__ float sA[32][33], sB[32][33];
    const int b = b0 + blockIdx.z;
    const float* Ab = A + (size_t)b * H * H;
    __half* sh = g_sh + (size_t)b * H * H;
    __half* sl = g_sl + (size_t)b * H * H;
    const int t = threadIdx.x;
    const int j0 = jt * 32, k0 = kt * 32;
    {
        const int r = t >> 3, q = t & 7;
        float4 va = *reinterpret_cast<const float4*>(Ab + (size_t)(j0 + r) * H + k0 + q * 4);
        sA[r][q * 4 + 0] = va.x; sA[r][q * 4 + 1] = va.y;
        sA[r][q * 4 + 2] = va.z; sA[r][q * 4 + 3] = va.w;
        float4 vb = *reinterpret_cast<const float4*>(Ab + (size_t)(k0 + r) * H + j0 + q * 4);
        sB[r][q * 4 + 0] = vb.x; sB[r][q * 4 + 1] = vb.y;
        sB[r][q * 4 + 2] = vb.z; sB[r][q * 4 + 3] = vb.w;
    }
    __syncthreads();
    const int r16 = t >> 4, cp = t & 15;
#pragma unroll
    for (int rr = 0; rr < 2; rr++) {
        const int row = rr * 16 + r16;
        float s0 = 0.5f * (sA[row][2 * cp]     + sB[2 * cp][row]);
        float s1 = 0.5f * (sA[row][2 * cp + 1] + sB[2 * cp + 1][row]);
        uint32_t hi, lo;
        split2(s0, s1, hi, lo);
        size_t off = (size_t)(j0 + row) * H + k0 + 2 * cp;
        *reinterpret_cast<uint32_t*>(sh + off) = hi;
        *reinterpret_cast<uint32_t*>(sl + off) = lo;
        if (jt != kt) {
            float t0 = 0.5f * (sB[row][2 * cp]     + sA[2 * cp][row]);
            float t1 = 0.5f * (sB[row][2 * cp + 1] + sA[2 * cp + 1][row]);
            split2(t0, t1, hi, lo);
            size_t off2 = (size_t)(k0 + row) * H + j0 + 2 * cp;
            *reinterpret_cast<uint32_t*>(sh + off2) = hi;
            *reinterpret_cast<uint32_t*>(sl + off2) = lo;
        }
    }
}

// ---------------- cvt: op fp32 -> fp16 hi/lo, + zero logits ----------------
__global__ void Measurement_68307159875839_cvt(const float* __restrict__ src,
                                               __half* __restrict__ dst_hi,
                                               __half* __restrict__ dst_lo, int n4) {
    int idx = blockIdx.x * blockDim.x + threadIdx.x;
    if (idx < BATCHN * H) g_logits[idx] = 0.0f;
    if (idx >= n4) return;
    float4 v = reinterpret_cast<const float4*>(src)[idx];
    uint32_t h0, l0, h1, l1;
    split2(v.x, v.y, h0, l0);
    split2(v.z, v.w, h1, l1);
    reinterpret_cast<uint2*>(dst_hi)[idx] = make_uint2(h0, h1);
    reinterpret_cast<uint2*>(dst_lo)[idx] = make_uint2(l0, l1);
}

// ---------------- GEMM (2 products; G2 in f16-acc) + fused diag ----------------
__device__ __forceinline__ void fill_stage(uint32_t smem_base, int t, int i0, int ct_base,
                                           size_t s_off, int tid) {
    const int n0 = (ct_base + t / NSEG) * TNO;
    const int k0 = (t % NSEG) * TKC;
    const int s = t % NSTAGE;
#pragma unroll
    for (int r = 0; r < 6; r++) {
        int q = r * NTHREADS + tid;
        int tile = q >> 9;
        int rem = q & 511;
        int row = rem >> 2;
        int c = rem & 3;
        uint32_t dst = smem_base + (uint32_t)(s * STAGE_B + tile * TILE_B + row * ROWB + c * 16);
        const __half* src;
        if (tile == 0)      src = g_op_hi + (size_t)(i0 + row) * H + k0 + c * 8;
        else if (tile == 1) src = g_sh + s_off + (size_t)(n0 + row) * H + k0 + c * 8;
        else                src = g_sl + s_off + (size_t)(n0 + row) * H + k0 + c * 8;
        cp16(dst, src);
    }
}

// grid: (18, CHUNK_B); x = i-tile (6) x ct-pair (3); y = batch-in-chunk.
__global__ void __launch_bounds__(NTHREADS)
Measurement_68307159875839_gemm(const float* __restrict__ op, int b0) {
    extern __shared__ __align__(16) char smem[];
    const uint32_t smem_base = smem_u32(smem);
    const int tid = threadIdx.x;
    const int lane = tid & 31;
    const int w = tid >> 5;
    const int mw = w >> 2;
    const int nw = w & 3;
    const int i0 = (blockIdx.x % 6) * TM;
    const int ct_base = (blockIdx.x / 6) * CT_PER_TASK;
    const int b = b0 + blockIdx.y;
    const size_t s_off = (size_t)b * H * H;

    const uint32_t a_off = (uint32_t)((mw * 64 + (lane & 15)) * ROWB + (lane >> 4) * 16);
    const uint32_t b_off = (uint32_t)((nw * 32 + (lane & 7) + ((lane & 16) >> 1)) * ROWB +
                                      ((lane >> 3) & 1) * 16);

    float part_acc[4][2];
#pragma unroll
    for (int mt = 0; mt < 4; mt++) { part_acc[mt][0] = 0.f; part_acc[mt][1] = 0.f; }

    float accG1[4][4][4];
    uint32_t accG2[4][4][2];
#pragma unroll
    for (int mt = 0; mt < 4; mt++)
#pragma unroll
        for (int nt = 0; nt < 4; nt++) {
#pragma unroll
            for (int e = 0; e < 4; e++) accG1[mt][nt][e] = 0.f;
            accG2[mt][nt][0] = 0u; accG2[mt][nt][1] = 0u;
        }

    fill_stage(smem_base, 0, i0, ct_base, s_off, tid); cp_commit();
    fill_stage(smem_base, 1, i0, ct_base, s_off, tid); cp_commit();

    for (int t = 0; t < NT; ++t) {
        if (t + 1 < NT) cp_wait1(); else cp_wait0();
        __syncthreads();

        const uint32_t sb = smem_base + (uint32_t)((t % NSTAGE) * STAGE_B);
#pragma unroll
        for (int k16 = 0; k16 < 2; k16++) {
            const uint32_t kofs = (uint32_t)(k16 * 32);
            uint32_t ah[4][4];
#pragma unroll
            for (int mt = 0; mt < 4; mt++)
                ldsm4(ah[mt], sb + OFF_H + a_off + mt * 16 * ROWB + kofs);
            uint32_t bh[4][2], bl[4][2];
#pragma unroll
            for (int u = 0; u < 2; u++) {
                uint32_t r4[4];
                ldsm4(r4, sb + OFF_SH + b_off + u * 16 * ROWB + kofs);
                bh[2 * u][0] = r4[0]; bh[2 * u][1] = r4[1];
                bh[2 * u + 1][0] = r4[2]; bh[2 * u + 1][1] = r4[3];
                ldsm4(r4, sb + OFF_SL + b_off + u * 16 * ROWB + kofs);
                bl[2 * u][0] = r4[0]; bl[2 * u][1] = r4[1];
                bl[2 * u + 1][0] = r4[2]; bl[2 * u + 1][1] = r4[3];
            }
#pragma unroll
            for (int mt = 0; mt < 4; mt++)
#pragma unroll
                for (int nt = 0; nt < 4; nt++)
                    mma16816(accG1[mt][nt], ah[mt], bh[nt]);
#pragma unroll
            for (int mt = 0; mt < 4; mt++)
#pragma unroll
                for (int nt = 0; nt < 4; nt++)
                    mma16816h(accG2[mt][nt], ah[mt], bl[nt]);
        }
        if (t + 2 < NT) { fill_stage(smem_base, t + 2, i0, ct_base, s_off, tid); cp_commit(); }

        if ((t % NSEG) == NSEG - 1) {
            const int n0 = (ct_base + t / NSEG) * TNO;
#pragma unroll
            for (int mt = 0; mt < 4; mt++)
#pragma unroll
                for (int ir = 0; ir < 2; ir++) {
                    const int i_g = i0 + mw * 64 + mt * 16 + (lane >> 2) + ir * 8;
                    const size_t base = (size_t)i_g * H + n0 + nw * 32 + (lane & 3) * 2;
                    const float* oprow = op + base;
                    const __half* olrow = g_op_lo + base;
                    float s = 0.f;
#pragma unroll
                    for (int nt = 0; nt < 4; nt++) {
                        float2 w2 = *reinterpret_cast<const float2*>(oprow + nt * 8);
                        __half2 lh = *reinterpret_cast<const __half2*>(olrow + nt * 8);
                        float2 l2 = __half22float2(lh);
                        __half2 g2h = *reinterpret_cast<__half2*>(&accG2[mt][nt][ir]);
                        float2 g2 = __half22float2(g2h);
                        s += accG1[mt][nt][ir * 2 + 0] * (w2.x + l2.x)
                           + accG1[mt][nt][ir * 2 + 1] * (w2.y + l2.y)
                           + g2.x * w2.x + g2.y * w2.y;
                    }
                    part_acc[mt][ir] += s;
#pragma unroll
                    for (int nt = 0; nt < 4; nt++) {
                        accG1[mt][nt][ir * 2 + 0] = 0.f; accG1[mt][nt][ir * 2 + 1] = 0.f;
                        accG2[mt][nt][ir] = 0u;
                    }
                }
        }
    }

#pragma unroll
    for (int mt = 0; mt < 4; mt++)
#pragma unroll
        for (int ir = 0; ir < 2; ir++) {
            float v = part_acc[mt][ir];
            v += __shfl_xor_sync(0xffffffffu, v, 1);
            v += __shfl_xor_sync(0xffffffffu, v, 2);
            part_acc[mt][ir] = v;
        }
    float* sp = reinterpret_cast<float*>(smem + OFF_SP);
    if ((lane & 3) == 0) {
#pragma unroll
        for (int mt = 0; mt < 4; mt++)
#pragma unroll
            for (int ir = 0; ir < 2; ir++) {
                int i_loc = mw * 64 + mt * 16 + (lane >> 2) + ir * 8;
                sp[nw * 128 + i_loc] = part_acc[mt][ir];
            }
    }
    __syncthreads();
    for (int i = tid; i < TM; i += NTHREADS)
        atomicAdd(&g_logits[b * H + i0 + i],
                  (sp[i] + sp[128 + i]) + (sp[256 + i] + sp[384 + i]));
}

// ---------------- softmax ----------------
__global__ void Measurement_68307159875839_softmax(float* __restrict__ out) {
    __shared__ float red[NTHREADS / 32];
    const int b = blockIdx.x, tid = threadIdx.x;
    const float* row = g_logits + b * H;
    float m = -1e30f;
    for (int i = tid; i < H; i += NTHREADS) m = fmaxf(m, row[i]);
#pragma unroll
    for (int o = 16; o > 0; o >>= 1) m = fmaxf(m, __shfl_xor_sync(0xffffffffu, m, o));
    if ((tid & 31) == 0) red[tid >> 5] = m;
    __syncthreads();
    m = red[0];
#pragma unroll
    for (int wv = 1; wv < NTHREADS / 32; wv++) m = fmaxf(m, red[wv]);
    __syncthreads();
    float s = 0.0f;
    for (int i = tid; i < H; i += NTHREADS) s += __expf(row[i] - m);
#pragma unroll
    for (int o = 16; o > 0; o >>= 1) s += __shfl_xor_sync(0xffffffffu, s, o);
    if ((tid & 31) == 0) red[tid >> 5] = s;
    __syncthreads();
    s = 0.0f;
#pragma unroll
    for (int wv = 0; wv < NTHREADS / 32; wv++) s += red[wv];
    const float inv = 1.0f / s;
    for (int i = tid; i < H; i += NTHREADS) out[b * H + i] = __expf(row[i] - m) * inv;
}

extern "C" void kernel_launch(void* const* d_in, const int* in_sizes, int n_in,
                              void* d_out, int out_size) {
    const float* inputs = (const float*)d_in[0];   // [128, 768, 768] fp32
    const float* op     = (const float*)d_in[1];   // [768, 768] fp32
    float* out = (float*)d_out;                    // [128, 768] fp32

    static int configured = 0;
    static cudaStream_t s2;
    static cudaEvent_t evFork;
    static cudaEvent_t evSym[NCHUNK];
    if (!configured) {
        cudaFuncSetAttribute(Measurement_68307159875839_gemm,
                             cudaFuncAttributeMaxDynamicSharedMemorySize, SMEM_TOTAL);
        cudaStreamCreateWithFlags(&s2, cudaStreamNonBlocking);
        cudaEventCreateWithFlags(&evFork, cudaEventDisableTiming);
        for (int c = 0; c < NCHUNK; c++)
            cudaEventCreateWithFlags(&evSym[c], cudaEventDisableTiming);
        configured = 1;
    }
    __half *op_hi, *op_lo;
    cudaGetSymbolAddress((void**)&op_hi, g_op_hi);
    cudaGetSymbolAddress((void**)&op_lo, g_op_lo);

    // fork: side stream s2 runs the sym chunks; main stream runs cvt then gemm chunks
    cudaEventRecord(evFork, 0);
    cudaStreamWaitEvent(s2, evFork, 0);

    const int n4_op = H * H / 4;
    Measurement_68307159875839_cvt<<<(n4_op + 255) / 256, 256>>>(op, op_hi, op_lo, n4_op);

    for (int c = 0; c < NCHUNK; c++) {
        Measurement_68307159875839_sym<<<dim3(H / 32, H / 32, CHUNK_B), 256, 0, s2>>>(
            inputs, c * CHUNK_B);
        cudaEventRecord(evSym[c], s2);
    }
    for (int c = 0; c < NCHUNK; c++) {
        cudaStreamWaitEvent(0, evSym[c], 0);
        Measurement_68307159875839_gemm<<<dim3(NXB, CHUNK_B), NTHREADS, SMEM_TOTAL>>>(
            op, c * CHUNK_B);
    }
    Measurement_68307159875839_softmax<<<BATCHN, NTHREADS>>>(out);
}

// round 10
// speedup vs baseline: 1.3550x; 1.0625x over previous
#include <cuda_runtime.h>
#include <cuda_fp16.h>
#include <cstdint>

#define H 768
#define BATCHN 128
#define NCHUNK 4
#define CHUNK_B (BATCHN / NCHUNK)   // 32
#define TM 128
#define TNO 64
#define TKC 32
#define NSEG (H / TKC)          // 24
#define CT_PER_TASK 2
#define NT (CT_PER_TASK * NSEG) // 48 steps per task
#define NXB ((H / TM) * (H / TNO / CT_PER_TASK))   // 6 * 6 = 36
#define NTHREADS 256

// SMEM per stage: h tile 128 rows, sh/sl tiles 64 rows; 80B pitch
#define ROWB 80
#define OFF_H  0
#define OFF_SH (128 * ROWB)              // 10240
#define OFF_SL (OFF_SH + 64 * ROWB)      // 15360
#define STAGE_B (OFF_SL + 64 * ROWB)     // 20480
#define NSTAGE 3
#define OFF_SP (NSTAGE * STAGE_B)        // 61440; partials 2*128 floats
#define SMEM_TOTAL (OFF_SP + 2 * 128 * 4)  // 62464 -> 2 CTAs/SM

__device__ float g_logits[BATCHN * H];
__device__ __half g_sh[(size_t)BATCHN * H * H];
__device__ __half g_sl[(size_t)BATCHN * H * H];
__device__ __half g_op_hi[H * H];
__device__ __half g_op_lo[H * H];

// ---------------- helpers ----------------
__device__ __forceinline__ uint32_t smem_u32(const void* p) {
    uint32_t a;
    asm("{ .reg .u64 t; cvta.to.shared.u64 t, %1; cvt.u32.u64 %0, t; }" : "=r"(a) : "l"(p));
    return a;
}
__device__ __forceinline__ void ldsm4(uint32_t* r, uint32_t addr) {
    asm volatile("ldmatrix.sync.aligned.m8n8.x4.shared.b16 {%0,%1,%2,%3}, [%4];"
                 : "=r"(r[0]), "=r"(r[1]), "=r"(r[2]), "=r"(r[3]) : "r"(addr));
}
__device__ __forceinline__ void mma16816(float* d, const uint32_t* a, const uint32_t* b) {
    asm volatile(
        "mma.sync.aligned.m16n8k16.row.col.f32.f16.f16.f32 "
        "{%0,%1,%2,%3}, {%4,%5,%6,%7}, {%8,%9}, {%0,%1,%2,%3};"
        : "+f"(d[0]), "+f"(d[1]), "+f"(d[2]), "+f"(d[3])
        : "r"(a[0]), "r"(a[1]), "r"(a[2]), "r"(a[3]), "r"(b[0]), "r"(b[1]));
}
__device__ __forceinline__ void mma16816h(uint32_t* d, const uint32_t* a, const uint32_t* b) {
    asm volatile(
        "mma.sync.aligned.m16n8k16.row.col.f16.f16.f16.f16 "
        "{%0,%1}, {%2,%3,%4,%5}, {%6,%7}, {%0,%1};"
        : "+r"(d[0]), "+r"(d[1])
        : "r"(a[0]), "r"(a[1]), "r"(a[2]), "r"(a[3]), "r"(b[0]), "r"(b[1]));
}
__device__ __forceinline__ void cp16(uint32_t dst, const void* src) {
    asm volatile("cp.async.cg.shared.global [%0], [%1], 16;" :: "r"(dst), "l"(src));
}
__device__ __forceinline__ void cp_commit() { asm volatile("cp.async.commit_group;" ::: "memory"); }
__device__ __forceinline__ void cp_wait1()  { asm volatile("cp.async.wait_group 1;" ::: "memory"); }
__device__ __forceinline__ void cp_wait0()  { asm volatile("cp.async.wait_group 0;" ::: "memory"); }
__device__ __forceinline__ uint32_t pack2(__half a, __half b) {
    __half2 h = __halves2half2(a, b);
    return *reinterpret_cast<uint32_t*>(&h);
}
__device__ __forceinline__ void split2(float s0, float s1, uint32_t& hi, uint32_t& lo) {
    __half h0 = __float2half_rn(s0), h1 = __float2half_rn(s1);
    __half l0 = __float2half_rn(s0 - __half2float(h0));
    __half l1 = __float2half_rn(s1 - __half2float(h1));
    hi = pack2(h0, h1);
    lo = pack2(l0, l1);
}

// ---------------- sym: symmetrize inputs chunk + fp16 hi/lo split ----------------
__global__ void __launch_bounds__(256)
Measurement_68307159875839_sym(const float* __restrict__ A, int b0) {
    const int jt = blockIdx.x, kt = blockIdx.y;
    if (jt > kt) return;
    __shared__ float sA[32][33], sB[32][33];
    const int b = b0 + blockIdx.z;
    const float* Ab = A + (size_t)b * H * H;
    __half* sh = g_sh + (size_t)b * H * H;
    __half* sl = g_sl + (size_t)b * H * H;
    const int t = threadIdx.x;
    const int j0 = jt * 32, k0 = kt * 32;
    {
        const int r = t >> 3, q = t & 7;
        float4 va = *reinterpret_cast<const float4*>(Ab + (size_t)(j0 + r) * H + k0 + q * 4);
        sA[r][q * 4 + 0] = va.x; sA[r][q * 4 + 1] = va.y;
        sA[r][q * 4 + 2] = va.z; sA[r][q * 4 + 3] = va.w;
        float4 vb = *reinterpret_cast<const float4*>(Ab + (size_t)(k0 + r) * H + j0 + q * 4);
        sB[r][q * 4 + 0] = vb.x; sB[r][q * 4 + 1] = vb.y;
        sB[r][q * 4 + 2] = vb.z; sB[r][q * 4 + 3] = vb.w;
    }
    __syncthreads();
    const int r16 = t >> 4, cp = t & 15;
#pragma unroll
    for (int rr = 0; rr < 2; rr++) {
        const int row = rr * 16 + r16;
        float s0 = 0.5f * (sA[row][2 * cp]     + sB[2 * cp][row]);
        float s1 = 0.5f * (sA[row][2 * cp + 1] + sB[2 * cp + 1][row]);
        uint32_t hi, lo;
        split2(s0, s1, hi, lo);
        size_t off = (size_t)(j0 + row) * H + k0 + 2 * cp;
        *reinterpret_cast<uint32_t*>(sh + off) = hi;
        *reinterpret_cast<uint32_t*>(sl + off) = lo;
        if (jt != kt) {
            float t0 = 0.5f * (sB[row][2 * cp]     + sA[2 * cp][row]);
            float t1 = 0.5f * (sB[row][2 * cp + 1] + sA[2 * cp + 1][row]);
            split2(t0, t1, hi, lo);
            size_t off2 = (size_t)(k0 + row) * H + j0 + 2 * cp;
            *reinterpret_cast<uint32_t*>(sh + off2) = hi;
            *reinterpret_cast<uint32_t*>(sl + off2) = lo;
        }
    }
}

// ---------------- cvt: op fp32 -> fp16 hi/lo, + zero logits ----------------
__global__ void Measurement_68307159875839_cvt(const float* __restrict__ src,
                                               __half* __restrict__ dst_hi,
                                               __half* __restrict__ dst_lo, int n4) {
    int idx = blockIdx.x * blockDim.x + threadIdx.x;
    if (idx < BATCHN * H) g_logits[idx] = 0.0f;
    if (idx >= n4) return;
    float4 v = reinterpret_cast<const float4*>(src)[idx];
    uint32_t h0, l0, h1, l1;
    split2(v.x, v.y, h0, l0);
    split2(v.z, v.w, h1, l1);
    reinterpret_cast<uint2*>(dst_hi)[idx] = make_uint2(h0, h1);
    reinterpret_cast<uint2*>(dst_lo)[idx] = make_uint2(l0, l1);
}

// ---------------- GEMM (2 products; G2 in f16-acc) + fused diag ----------------
// per stage: h 128 rows (512 chunks), sh 64 rows (256), sl 64 rows (256) = 1024 chunks
__device__ __forceinline__ void fill_stage(uint32_t smem_base, int t, int i0, int ct_base,
                                           size_t s_off, int tid) {
    const int n0 = (ct_base + t / NSEG) * TNO;
    const int k0 = (t % NSEG) * TKC;
    const int s = t % NSTAGE;
#pragma unroll
    for (int r = 0; r < 4; r++) {
        int q = r * NTHREADS + tid;
        const __half* src;
        uint32_t off;
        if (q < 512) {
            int row = q >> 2, c = q & 3;
            off = OFF_H + row * ROWB + c * 16;
            src = g_op_hi + (size_t)(i0 + row) * H + k0 + c * 8;
        } else if (q < 768) {
            int row = (q - 512) >> 2, c = q & 3;
            off = OFF_SH + row * ROWB + c * 16;
            src = g_sh + s_off + (size_t)(n0 + row) * H + k0 + c * 8;
        } else {
            int row = (q - 768) >> 2, c = q & 3;
            off = OFF_SL + row * ROWB + c * 16;
            src = g_sl + s_off + (size_t)(n0 + row) * H + k0 + c * 8;
        }
        cp16(smem_base + (uint32_t)(s * STAGE_B) + off, src);
    }
}

// grid: (36, CHUNK_B); x = i-tile (6) x ct-group (6); y = batch-in-chunk.
// 8 warps: 4 M-warps x 2 N-warps; warp tile 32x32.
__global__ void __launch_bounds__(NTHREADS, 2)
Measurement_68307159875839_gemm(const float* __restrict__ op, int b0) {
    extern __shared__ __align__(16) char smem[];
    const uint32_t smem_base = smem_u32(smem);
    const int tid = threadIdx.x;
    const int lane = tid & 31;
    const int w = tid >> 5;
    const int mw = w >> 1;         // 4 M-warps: 32 rows each
    const int nw = w & 1;          // 2 N-warps: 32 cols each
    const int i0 = (blockIdx.x % 6) * TM;
    const int ct_base = (blockIdx.x / 6) * CT_PER_TASK;
    const int b = b0 + blockIdx.y;
    const size_t s_off = (size_t)b * H * H;

    const uint32_t a_off = (uint32_t)(OFF_H + (mw * 32 + (lane & 15)) * ROWB + (lane >> 4) * 16);
    const uint32_t b_row = (uint32_t)(nw * 32 + (lane & 7) + ((lane & 16) >> 1));
    const uint32_t b_col = (uint32_t)(((lane >> 3) & 1) * 16);

    float part_acc[2][2];
#pragma unroll
    for (int mt = 0; mt < 2; mt++) { part_acc[mt][0] = 0.f; part_acc[mt][1] = 0.f; }

    float accG1[2][4][4];
    uint32_t accG2[2][4][2];
#pragma unroll
    for (int mt = 0; mt < 2; mt++)
#pragma unroll
        for (int nt = 0; nt < 4; nt++) {
#pragma unroll
            for (int e = 0; e < 4; e++) accG1[mt][nt][e] = 0.f;
            accG2[mt][nt][0] = 0u; accG2[mt][nt][1] = 0u;
        }

    fill_stage(smem_base, 0, i0, ct_base, s_off, tid); cp_commit();
    fill_stage(smem_base, 1, i0, ct_base, s_off, tid); cp_commit();

    for (int t = 0; t < NT; ++t) {
        if (t + 1 < NT) cp_wait1(); else cp_wait0();
        __syncthreads();

        const uint32_t sb = smem_base + (uint32_t)((t % NSTAGE) * STAGE_B);
#pragma unroll
        for (int k16 = 0; k16 < 2; k16++) {
            const uint32_t kofs = (uint32_t)(k16 * 32);
            uint32_t ah[2][4];
#pragma unroll
            for (int mt = 0; mt < 2; mt++)
                ldsm4(ah[mt], sb + a_off + mt * 16 * ROWB + kofs);
            uint32_t bh[4][2], bl[4][2];
#pragma unroll
            for (int u = 0; u < 2; u++) {
                uint32_t r4[4];
                ldsm4(r4, sb + OFF_SH + (b_row + u * 16) * ROWB + b_col + kofs);
                bh[2 * u][0] = r4[0]; bh[2 * u][1] = r4[1];
                bh[2 * u + 1][0] = r4[2]; bh[2 * u + 1][1] = r4[3];
                ldsm4(r4, sb + OFF_SL + (b_row + u * 16) * ROWB + b_col + kofs);
                bl[2 * u][0] = r4[0]; bl[2 * u][1] = r4[1];
                bl[2 * u + 1][0] = r4[2]; bl[2 * u + 1][1] = r4[3];
            }
#pragma unroll
            for (int mt = 0; mt < 2; mt++)
#pragma unroll
                for (int nt = 0; nt < 4; nt++)
                    mma16816(accG1[mt][nt], ah[mt], bh[nt]);
#pragma unroll
            for (int mt = 0; mt < 2; mt++)
#pragma unroll
                for (int nt = 0; nt < 4; nt++)
                    mma16816h(accG2[mt][nt], ah[mt], bl[nt]);
        }
        if (t + 2 < NT) { fill_stage(smem_base, t + 2, i0, ct_base, s_off, tid); cp_commit(); }

        if ((t % NSEG) == NSEG - 1) {
            const int n0 = (ct_base + t / NSEG) * TNO;
#pragma unroll
            for (int mt = 0; mt < 2; mt++)
#pragma unroll
                for (int ir = 0; ir < 2; ir++) {
                    const int i_g = i0 + mw * 32 + mt * 16 + (lane >> 2) + ir * 8;
                    const size_t base = (size_t)i_g * H + n0 + nw * 32 + (lane & 3) * 2;
                    const float* oprow = op + base;
                    const __half* olrow = g_op_lo + base;
                    float s = 0.f;
#pragma unroll
                    for (int nt = 0; nt < 4; nt++) {
                        float2 w2 = *reinterpret_cast<const float2*>(oprow + nt * 8);
                        __half2 lh = *reinterpret_cast<const __half2*>(olrow + nt * 8);
                        float2 l2 = __half22float2(lh);
                        __half2 g2h = *reinterpret_cast<__half2*>(&accG2[mt][nt][ir]);
                        float2 g2 = __half22float2(g2h);
                        s += accG1[mt][nt][ir * 2 + 0] * (w2.x + l2.x)
                           + accG1[mt][nt][ir * 2 + 1] * (w2.y + l2.y)
                           + g2.x * w2.x + g2.y * w2.y;
                    }
                    part_acc[mt][ir] += s;
#pragma unroll
                    for (int nt = 0; nt < 4; nt++) {
                        accG1[mt][nt][ir * 2 + 0] = 0.f; accG1[mt][nt][ir * 2 + 1] = 0.f;
                        accG2[mt][nt][ir] = 0u;
                    }
                }
        }
    }

    // reduce 4 lanes sharing i, combine 2 nw warps via smem, one atomicAdd per i
#pragma unroll
    for (int mt = 0; mt < 2; mt++)
#pragma unroll
        for (int ir = 0; ir < 2; ir++) {
            float v = part_acc[mt][ir];
            v += __shfl_xor_sync(0xffffffffu, v, 1);
            v += __shfl_xor_sync(0xffffffffu, v, 2);
            part_acc[mt][ir] = v;
        }
    float* sp = reinterpret_cast<float*>(smem + OFF_SP);
    if ((lane & 3) == 0) {
#pragma unroll
        for (int mt = 0; mt < 2; mt++)
#pragma unroll
            for (int ir = 0; ir < 2; ir++) {
                int i_loc = mw * 32 + mt * 16 + (lane >> 2) + ir * 8;
                sp[nw * 128 + i_loc] = part_acc[mt][ir];
            }
    }
    __syncthreads();
    for (int i = tid; i < TM; i += NTHREADS)
        atomicAdd(&g_logits[b * H + i0 + i], sp[i] + sp[128 + i]);
}

// ---------------- softmax ----------------
__global__ void Measurement_68307159875839_softmax(float* __restrict__ out) {
    __shared__ float red[NTHREADS / 32];
    const int b = blockIdx.x, tid = threadIdx.x;
    const float* row = g_logits + b * H;
    float m = -1e30f;
    for (int i = tid; i < H; i += NTHREADS) m = fmaxf(m, row[i]);
#pragma unroll
    for (int o = 16; o > 0; o >>= 1) m = fmaxf(m, __shfl_xor_sync(0xffffffffu, m, o));
    if ((tid & 31) == 0) red[tid >> 5] = m;
    __syncthreads();
    m = red[0];
#pragma unroll
    for (int wv = 1; wv < NTHREADS / 32; wv++) m = fmaxf(m, red[wv]);
    __syncthreads();
    float s = 0.0f;
    for (int i = tid; i < H; i += NTHREADS) s += __expf(row[i] - m);
#pragma unroll
    for (int o = 16; o > 0; o >>= 1) s += __shfl_xor_sync(0xffffffffu, s, o);
    if ((tid & 31) == 0) red[tid >> 5] = s;
    __syncthreads();
    s = 0.0f;
#pragma unroll
    for (int wv = 0; wv < NTHREADS / 32; wv++) s += red[wv];
    const float inv = 1.0f / s;
    for (int i = tid; i < H; i += NTHREADS) out[b * H + i] = __expf(row[i] - m) * inv;
}

extern "C" void kernel_launch(void* const* d_in, const int* in_sizes, int n_in,
                              void* d_out, int out_size) {
    const float* inputs = (const float*)d_in[0];   // [128, 768, 768] fp32
    const float* op     = (const float*)d_in[1];   // [768, 768] fp32
    float* out = (float*)d_out;                    // [128, 768] fp32

    static int configured = 0;
    static cudaStream_t s2;
    static cudaEvent_t evFork;
    static cudaEvent_t evSym[NCHUNK];
    if (!configured) {
        cudaFuncSetAttribute(Measurement_68307159875839_gemm,
                             cudaFuncAttributeMaxDynamicSharedMemorySize, SMEM_TOTAL);
        cudaStreamCreateWithFlags(&s2, cudaStreamNonBlocking);
        cudaEventCreateWithFlags(&evFork, cudaEventDisableTiming);
        for (int c = 0; c < NCHUNK; c++)
            cudaEventCreateWithFlags(&evSym[c], cudaEventDisableTiming);
        configured = 1;
    }
    __half *op_hi, *op_lo;
    cudaGetSymbolAddress((void**)&op_hi, g_op_hi);
    cudaGetSymbolAddress((void**)&op_lo, g_op_lo);

    cudaEventRecord(evFork, 0);
    cudaStreamWaitEvent(s2, evFork, 0);

    const int n4_op = H * H / 4;
    Measurement_68307159875839_cvt<<<(n4_op + 255) / 256, 256>>>(op, op_hi, op_lo, n4_op);

    for (int c = 0; c < NCHUNK; c++) {
        Measurement_68307159875839_sym<<<dim3(H / 32, H / 32, CHUNK_B), 256, 0, s2>>>(
            inputs, c * CHUNK_B);
        cudaEventRecord(evSym[c], s2);
    }
    for (int c = 0; c < NCHUNK; c++) {
        cudaStreamWaitEvent(0, evSym[c], 0);
        Measurement_68307159875839_gemm<<<dim3(NXB, CHUNK_B), NTHREADS, SMEM_TOTAL>>>(
            op, c * CHUNK_B);
    }
    Measurement_68307159875839_softmax<<<BATCHN, NTHREADS>>>(out);
}